// round 15
// baseline (speedup 1.0000x reference)
#include <cuda_runtime.h>

#define W 224
#define H 224
#define BC 192
#define STEPS 32
#define RPB 39              // 6 bands: 0-4 = 39 full rows, band 5 = 28 full + bottom
#define TPB 256
#define NW 8
#define GRID (BC * 3)       // 576; block = (bc, pair k) with streams band k & k+3

// g_hist[bc][j] accumulates the cumulative Euler characteristic at t_j.
__device__ int g_hist[BC * STEPS];
__device__ unsigned int g_count;

template <int IMM>
__device__ __forceinline__ unsigned lop3(unsigned a, unsigned b, unsigned c) {
    unsigned r;
    asm("lop3.b32 %0, %1, %2, %3, %4;" : "=r"(r) : "r"(a), "r"(b), "r"(c), "n"(IMM));
    return r;
}

// Alive mask: bit j set iff t_j >= f. ceil-based fast binning (R14: rel_err 0.0).
__device__ __forceinline__ unsigned maskof(float f) {
    const int g = __float2int_ru(f * 31.0f);   // in [0, 31] for f in [0, 1)
    return 0xFFFFFFFFu << g;
}

__device__ __forceinline__ void csa5(unsigned c[5], unsigned x) {
    unsigned t;
    t = c[0] & x; c[0] ^= x; x = t;
    t = c[1] & x; c[1] ^= x; x = t;
    t = c[2] & x; c[2] ^= x; x = t;
    t = c[3] & x; c[3] ^= x; x = t;
    c[4] ^= x;
}

// Warp 32x32 bit transpose: out lane j bit k = in lane k bit j.
__device__ __forceinline__ unsigned tr32(unsigned v, int lane) {
    unsigned w;
    w = __shfl_xor_sync(0xffffffffu, v, 16);
    v = (lane & 16) ? ((v & 0xFFFF0000u) | ((w >> 16) & 0x0000FFFFu))
                    : ((v & 0x0000FFFFu) | ((w << 16) & 0xFFFF0000u));
    w = __shfl_xor_sync(0xffffffffu, v, 8);
    v = (lane & 8)  ? ((v & 0xFF00FF00u) | ((w >> 8)  & 0x00FF00FFu))
                    : ((v & 0x00FF00FFu) | ((w << 8)  & 0xFF00FF00u));
    w = __shfl_xor_sync(0xffffffffu, v, 4);
    v = (lane & 4)  ? ((v & 0xF0F0F0F0u) | ((w >> 4)  & 0x0F0F0F0Fu))
                    : ((v & 0x0F0F0F0Fu) | ((w << 4)  & 0xF0F0F0F0u));
    w = __shfl_xor_sync(0xffffffffu, v, 2);
    v = (lane & 2)  ? ((v & 0xCCCCCCCCu) | ((w >> 2)  & 0x33333333u))
                    : ((v & 0x33333333u) | ((w << 2)  & 0xCCCCCCCCu));
    w = __shfl_xor_sync(0xffffffffu, v, 1);
    v = (lane & 1)  ? ((v & 0xAAAAAAAAu) | ((w >> 1)  & 0x55555555u))
                    : ((v & 0x55555555u) | ((w << 1)  & 0xAAAAAAAAu));
    return v;
}

// One pixel row: P (net +1 cells) and NN = ~N (complemented net -1 cells).
__device__ __forceinline__ void rowPN(unsigned& m, unsigned& mr, float f,
                                      unsigned aM, unsigned hasRM,
                                      unsigned& P, unsigned& NN) {
    const unsigned mn  = maskof(f);
    const unsigned mnr = __shfl_down_sync(0xffffffffu, mn, 1);
    const unsigned mrE = lop3<0xE4>(mr, mn, hasRM);    // (mr&h)|(mn&~h)
    P  = lop3<0x20>(m, mrE, aM);                       // m & ~mrE & aM
    const unsigned t2  = lop3<0xD5>(mr, mnr, hasRM);   // (mr&mnr)|~h
    NN = lop3<0xBF>(m, mn, t2);                        // ~(m & mn & ~t2)
    m = mn; mr = mnr;
}

// 6:3 compress {Pa,Pb,Pc, Na,Nb,Nc} (N's complemented) into w1/w2/w4 planes.
__device__ __forceinline__ void add6(unsigned A1[5], unsigned A2[5], unsigned A4[5],
                                     unsigned Pa, unsigned Pb, unsigned Pc,
                                     unsigned Na, unsigned Nb, unsigned Nc) {
    unsigned sP = lop3<0x96>(Pa, Pb, Pc), cP = lop3<0xE8>(Pa, Pb, Pc);
    unsigned sN = lop3<0x96>(Na, Nb, Nc), cN = lop3<0xE8>(Na, Nb, Nc);
    unsigned s  = sP ^ sN, c3 = sP & sN;
    unsigned c  = lop3<0x96>(cP, cN, c3), d = lop3<0xE8>(cP, cN, c3);
    csa5(A1, s); csa5(A2, c); csa5(A4, d);
}

__global__ __launch_bounds__(TPB) void ecc_kernel(const float* __restrict__ x,
                                                  float* __restrict__ out) {
    __shared__ int s_cnt[NW][STEPS];
    __shared__ bool s_last;

    const int tid  = threadIdx.x;
    const int wid  = tid >> 5;
    const int lane = tid & 31;
    const int col  = wid * 31 + lane;           // overlapped-warp column map
    const int bc   = blockIdx.x / 3;
    const int k    = blockIdx.x % 3;            // pair index: bands k and k+3

    const bool act       = (lane < 31) && (col <= 223);
    const unsigned aM    = act ? 0xFFFFFFFFu : 0u;
    const unsigned hasRM = (act && col < 223) ? 0xFFFFFFFFu : 0u;
    const int colc = (col <= 223) ? col : 223;

    unsigned A1[5] = {0,0,0,0,0}, A2[5] = {0,0,0,0,0}, A4[5] = {0,0,0,0,0};

    const float* base = x + (size_t)bc * (H * W) + colc;
    const float* pA = base + (size_t)(RPB * k) * W;         // band k
    const float* pB = base + (size_t)(RPB * (k + 3)) * W;   // band k+3

    unsigned mA = maskof(__ldg(pA)), mB = maskof(__ldg(pB));
    unsigned mrA = __shfl_down_sync(0xffffffffu, mA, 1);
    unsigned mrB = __shfl_down_sync(0xffffffffu, mB, 1);

    // bands 0-4: 13 triples (39 rows); band 5: 9 triples (27 of 28 full rows).
    const int npair = (k == 2) ? 9 : 13;

    float a0 = __ldg(pA + W), a1 = __ldg(pA + 2 * W), a2 = __ldg(pA + 3 * W);
    float b0 = __ldg(pB + W), b1 = __ldg(pB + 2 * W), b2 = __ldg(pB + 3 * W);
    pA += 3 * W; pB += 3 * W;

#pragma unroll 2
    for (int it = 0; it < npair - 1; it++) {
        const float na0 = __ldg(pA + W), na1 = __ldg(pA + 2 * W), na2 = __ldg(pA + 3 * W);
        const float nb0 = __ldg(pB + W), nb1 = __ldg(pB + 2 * W), nb2 = __ldg(pB + 3 * W);
        pA += 3 * W; pB += 3 * W;
        unsigned Pa, Na, Pb, Nb, Pc, Nc;
        rowPN(mA, mrA, a0, aM, hasRM, Pa, Na);
        rowPN(mA, mrA, a1, aM, hasRM, Pb, Nb);
        rowPN(mA, mrA, a2, aM, hasRM, Pc, Nc);
        add6(A1, A2, A4, Pa, Pb, Pc, Na, Nb, Nc);
        rowPN(mB, mrB, b0, aM, hasRM, Pa, Na);
        rowPN(mB, mrB, b1, aM, hasRM, Pb, Nb);
        rowPN(mB, mrB, b2, aM, hasRM, Pc, Nc);
        add6(A1, A2, A4, Pa, Pb, Pc, Na, Nb, Nc);
        a0 = na0; a1 = na1; a2 = na2;
        b0 = nb0; b1 = nb1; b2 = nb2;
    }
    {   // final paired triple (pointers NOT advanced)
        unsigned Pa, Na, Pb, Nb, Pc, Nc;
        rowPN(mA, mrA, a0, aM, hasRM, Pa, Na);
        rowPN(mA, mrA, a1, aM, hasRM, Pb, Nb);
        rowPN(mA, mrA, a2, aM, hasRM, Pc, Nc);
        add6(A1, A2, A4, Pa, Pb, Pc, Na, Nb, Nc);
        rowPN(mB, mrB, b0, aM, hasRM, Pa, Na);
        rowPN(mB, mrB, b1, aM, hasRM, Pb, Nb);
        rowPN(mB, mrB, b2, aM, hasRM, Pc, Nc);
        add6(A1, A2, A4, Pa, Pb, Pc, Na, Nb, Nc);
    }

    int nN = 6 * npair;                 // complemented-N rows folded in so far
    if (k == 2) {
        // Stream A (band 2): 4 remaining triples (rows 105..116).
#pragma unroll
        for (int it = 0; it < 4; it++) {
            const float fa = __ldg(pA + W), fb = __ldg(pA + 2 * W), fc = __ldg(pA + 3 * W);
            pA += 3 * W;
            unsigned Pa, Na, Pb, Nb, Pc, Nc;
            rowPN(mA, mrA, fa, aM, hasRM, Pa, Na);
            rowPN(mA, mrA, fb, aM, hasRM, Pb, Nb);
            rowPN(mA, mrA, fc, aM, hasRM, Pc, Nc);
            add6(A1, A2, A4, Pa, Pb, Pc, Na, Nb, Nc);
        }
        nN += 12;
        // Stream B tail: pixel row 222 (full) + row 223 (vertex + h-edge only).
        unsigned Pa, Na;
        rowPN(mB, mrB, __ldg(pB + W), aM, hasRM, Pa, Na);
        const unsigned Pb = lop3<0x20>(mB, mrB & hasRM, aM);   // bottom row
        csa5(A1, lop3<0x96>(Pa, Na, Pb));
        csa5(A2, lop3<0xE8>(Pa, Na, Pb));
        nN += 1;
    }

    // Epilogue: transpose 15 planes, weighted popcounts, subtract the
    // complement offset (each ~N row contributed +1 to every bin, x32 lanes).
    int cnt = -(nN << 5);
#pragma unroll
    for (int i = 0; i < 5; i++) cnt += (int)__popc(tr32(A1[i], lane)) << i;
#pragma unroll
    for (int i = 0; i < 5; i++) cnt += (int)__popc(tr32(A2[i], lane)) << (i + 1);
#pragma unroll
    for (int i = 0; i < 5; i++) cnt += (int)__popc(tr32(A4[i], lane)) << (i + 2);

    s_cnt[wid][lane] = cnt;
    __syncthreads();
    if (wid == 0) {
        int sum = 0;
#pragma unroll
        for (int w2 = 0; w2 < NW; w2++) sum += s_cnt[w2][lane];
        atomicAdd(&g_hist[bc * STEPS + lane], sum);
    }

    // Last-block-done: write out + reset scratch for next graph replay.
    __threadfence();
    __syncthreads();
    if (tid == 0)
        s_last = (atomicAdd(&g_count, 1u) == (unsigned)(GRID - 1));
    __syncthreads();

    if (s_last) {
        __threadfence();
        for (int g2 = wid; g2 < BC; g2 += NW) {
            const int vv = __ldcg(&g_hist[g2 * STEPS + lane]);
            out[g2 * STEPS + lane] = (float)vv;
            g_hist[g2 * STEPS + lane] = 0;
        }
        if (tid == 0) g_count = 0u;
    }
}

extern "C" void kernel_launch(void* const* d_in, const int* in_sizes, int n_in,
                              void* d_out, int out_size) {
    const float* x = (const float*)d_in[0];
    float* out = (float*)d_out;
    (void)in_sizes; (void)n_in; (void)out_size;
    ecc_kernel<<<GRID, TPB>>>(x, out);
}